// round 15
// baseline (speedup 1.0000x reference)
#include <cuda_runtime.h>

#define Hh 51
#define NB 4
#define NTH 224
#define BTOT 512
#define ROWF 104                        // [0..50]=h1, [51]=x(t+1), [52..102]=h2, [103]=0
#define BUF_BYTES (NB * ROWF * 4)       // bytes per double-buffer half

__device__ __forceinline__ unsigned long long pack2(float lo, float hi) {
    unsigned long long r;
    asm("mov.b64 %0, {%1,%2};" : "=l"(r) : "f"(lo), "f"(hi));
    return r;
}
__device__ __forceinline__ void ffma2(unsigned long long &acc, unsigned long long a, unsigned long long b) {
    asm("fma.rn.f32x2 %0, %1, %2, %0;" : "+l"(acc) : "l"(a), "l"(b));
}
__device__ __forceinline__ float sum2(unsigned long long a) {
    float lo, hi;
    asm("mov.b64 {%0,%1}, %2;" : "=f"(lo), "=f"(hi) : "l"(a));
    return lo + hi;
}
__device__ __forceinline__ void lds128(unsigned long long &p0, unsigned long long &p1, unsigned addr) {
    asm volatile("ld.shared.v2.b64 {%0,%1}, [%2];" : "=l"(p0), "=l"(p1) : "r"(addr));
}
__device__ __forceinline__ float ftanh_(float x) {
    float r;
    asm("tanh.approx.f32 %0, %1;" : "=f"(r) : "f"(x));
    return r;
}
__device__ __forceinline__ float fsig(float x) {
    float r;
    asm("tanh.approx.f32 %0, %1;" : "=f"(r) : "f"(0.5f * x));
    return fmaf(0.5f, r, 0.5f);
}

// 4x4 transpose across lane bits 3..4 (gate <-> batch-slot).
__device__ __forceinline__ void transp4(float v[4], int lane) {
    {
        bool lo = lane & 8;
        float tA = lo ? v[0] : v[1];
        float tB = lo ? v[2] : v[3];
        tA = __shfl_xor_sync(0xffffffffu, tA, 8);
        tB = __shfl_xor_sync(0xffffffffu, tB, 8);
        if (lo) { v[0] = tA; v[2] = tB; } else { v[1] = tA; v[3] = tB; }
    }
    {
        bool hi = lane & 16;
        float uA = hi ? v[0] : v[2];
        float uB = hi ? v[1] : v[3];
        uA = __shfl_xor_sync(0xffffffffu, uA, 16);
        uB = __shfl_xor_sync(0xffffffffu, uB, 16);
        if (hi) { v[0] = uA; v[1] = uB; } else { v[2] = uA; v[3] = uB; }
    }
}

#define REDUCE_PBUF(dst) { \
    float4 s4 = make_float4(0.f, 0.f, 0.f, 0.f); \
    const float4* p4 = (const float4*)&pbuf[q][0]; \
    _Pragma("unroll") for (int k = 0; k < 12; ++k) { \
        float4 v4 = p4[k]; \
        s4.x += v4.x; s4.y += v4.y; s4.z += v4.z; s4.w += v4.w; } \
    (dst) = (s4.x + s4.y) + (s4.z + s4.w) \
          + pbuf[q][48] + pbuf[q][49] + pbuf[q][50] + blin; }

// One full timestep. CO/PO compile-time buffer byte-offsets; CI/PI buffer indices.
// x(t+1) is FOLDED into the jointdot via slot 51 (w1n[25].hi = wi1): pre_lane
// stores x(t+1) (or 0 in the AR region) into CI[51] in segment 1; B_A orders
// it before the jointdot. tail-1 is then sum2+transpose only. In the AR region
// the x-term is added from xs[] (written by red_lane at B_C).
#define STEP(t, CI, PI, CO, PO) { \
    /* pre_lane: publish x(t+1) (or 0 for AR) into cur slot 51; no seg-1 reader of CI[51] */ \
    if (pre_lane) { \
        hcat[CI][q][51] = ((t) + 1 < T) ? xpre : 0.f; \
        if ((t) + 2 < T) xpre = input[(b0 + q) * T + ((t) + 2)]; \
    } \
    /* tail-1 (independent of phase-A dot): layer-1 update from carried a1n */ \
    float v[4]; \
    _Pragma("unroll") for (int b = 0; b < NB; ++b) { \
        v[b] = sum2(a1n[b]); \
        if ((t) >= T) v[b] = fmaf(xs[b], wi1, v[b]);   /* AR: x = out(t-1) */ \
    } \
    transp4(v, lane); \
    { \
        float cg = fsig(v[1]) * c1 + fsig(v[0]) * ftanh_(v[2]); \
        c1 = cg; \
        float h1 = fsig(v[3]) * ftanh_(cg); \
        if (act) hcat[CI][q][j] = h1; \
    } \
    /* phase-A dot: a2 = bs2 + W_hh2 . h2(t-1)  (prev slots 52..103, static offsets) */ \
    unsigned long long a2[NB]; \
    _Pragma("unroll") for (int b = 0; b < NB; ++b) a2[b] = pack2(bs2, 0.f); \
    _Pragma("unroll") for (int kk = 0; kk < 13; ++kk) { \
        _Pragma("unroll") for (int b = 0; b < NB; ++b) { \
            unsigned long long q0, q1; \
            lds128(q0, q1, hb[b] + (PO) + 208u + kk * 16u); \
            ffma2(a2[b], w2p[26 + 2*kk], q0); \
            ffma2(a2[b], w2p[27 + 2*kk], q1); \
        } \
    } \
    /* red_lane deferred out(t-1): AFTER the dot so its LDS slot into issue gaps */ \
    if (red_lane && (t) >= 1 && (t) < T) { \
        float sres; REDUCE_PBUF(sres); \
        out[(b0 + q) * Ttot + ((t) - 1)] = sres; \
    } \
    __syncthreads();  /* B_A */ \
    /* phase B: joint dot over cur slots 0..51 (h1(t) + x(t+1) at slot 51) */ \
    _Pragma("unroll") for (int b = 0; b < NB; ++b) a1n[b] = pack2(bs1, 0.f); \
    _Pragma("unroll") for (int kk = 0; kk < 13; ++kk) { \
        _Pragma("unroll") for (int b = 0; b < NB; ++b) { \
            unsigned long long p0, p1; \
            lds128(p0, p1, hb[b] + (CO) + kk * 16u); \
            ffma2(a2[b],  w2p[2*kk],     p0); \
            ffma2(a2[b],  w2p[2*kk + 1], p1); \
            ffma2(a1n[b], w1n[2*kk],     p0); \
            ffma2(a1n[b], w1n[2*kk + 1], p1); \
        } \
    } \
    _Pragma("unroll") for (int b = 0; b < NB; ++b) v[b] = sum2(a2[b]); \
    transp4(v, lane); \
    { \
        float cg = fsig(v[1]) * c2 + fsig(v[0]) * ftanh_(v[2]); \
        c2 = cg; \
        float h2v = fsig(v[3]) * ftanh_(cg); \
        if (act) { \
            hcat[CI][q][52 + j] = h2v; \
            pbuf[q][j] = wl * h2v; \
        } \
    } \
    __syncthreads();  /* B_B */ \
    /* autoregressive feedback: out(t) -> xs (x for tail-1 of t+1) */ \
    if ((t) >= T - 1) { \
        if (red_lane) { \
            float sres; REDUCE_PBUF(sres); \
            out[(b0 + q) * Ttot + (t)] = sres; \
            xs[q] = sres; \
        } \
        __syncthreads();  /* B_C */ \
    } \
}

__global__ void __launch_bounds__(NTH, 1)
lstm2_kernel(const float* __restrict__ input,
             const float* __restrict__ W_ih1, const float* __restrict__ W_hh1,
             const float* __restrict__ b_ih1, const float* __restrict__ b_hh1,
             const float* __restrict__ W_ih2, const float* __restrict__ W_hh2,
             const float* __restrict__ b_ih2, const float* __restrict__ b_hh2,
             const float* __restrict__ W_lin, const float* __restrict__ b_lin,
             float* __restrict__ out, int T, int Ttot)
{
    __shared__ __align__(16) float hcat[2][NB][ROWF];   // double-buffered
    __shared__ __align__(16) float pbuf[NB][68];
    __shared__ float xs[NB];                             // x(0) at init; out-feedback in AR

    const int  tid  = threadIdx.x;
    const int  lane = tid & 31;
    const int  wid  = tid >> 5;
    const int  jloc = lane & 7;
    const int  q    = (lane >> 3) & 3;          // gate index for dots; batch index for update
    const int  j    = wid * 8 + jloc;
    const bool act  = (j < Hh);
    const int  b0   = blockIdx.x * NB;
    const int  row  = q * Hh + (act ? j : 0);

    const bool pre_lane = (wid == 6) && (jloc == 3);    // x publisher, batch q
    const bool red_lane = (wid == 6) && (jloc == 4);    // output reduction, batch q

    for (int i = tid; i < 2 * NB * ROWF; i += NTH) (&hcat[0][0][0])[i] = 0.f;
    if (tid < NB) xs[tid] = input[(b0 + tid) * T];      // x(0) (xs disjoint from hcat)

    // ---- weights, packed along K into 64-bit pairs (registers) ----
    // w1n : W_hh1 over slots 0..50; slot 51 -> wi1 (x folded into the jointdot)
    // w2p : layer-2 over slots 0..103 (0..50 = W_ih2 on h1, 51 -> 0, 52..102 = W_hh2, 103 -> 0)
    const float wi1 = act ? W_ih1[row] : 0.f;
    unsigned long long w1n[26], w2p[52];
    {
        const float* r1 = W_hh1 + row * Hh;
        #pragma unroll
        for (int k = 0; k < 26; ++k) {
            int k0 = 2*k, k1 = 2*k + 1;
            float a = (act && k0 < 51) ? r1[k0] : 0.f;
            float b = (act && k1 < 51) ? r1[k1] : ((k1 == 51) ? wi1 : 0.f);
            w1n[k] = pack2(a, b);
        }
        const float* ri = W_ih2 + row * Hh;   // multiplies h1
        const float* rh = W_hh2 + row * Hh;   // multiplies h2
        #pragma unroll
        for (int k = 0; k < 52; ++k) {
            int k0 = 2*k, k1 = 2*k + 1;
            float a = 0.f, b = 0.f;
            if (act) {
                a = (k0 < 51) ? ri[k0] : ((k0 >= 52 && k0 <= 102) ? rh[k0 - 52] : 0.f);
                b = (k1 < 51) ? ri[k1] : ((k1 >= 52 && k1 <= 102) ? rh[k1 - 52] : 0.f);
            }
            w2p[k] = pack2(a, b);
        }
    }
    const float bs1  = act ? (b_ih1[row] + b_hh1[row]) : 0.f;
    const float bs2  = act ? (b_ih2[row] + b_hh2[row]) : 0.f;
    const float wl   = act ? W_lin[j] : 0.f;
    const float blin = b_lin[0];

    unsigned hb[NB];
    #pragma unroll
    for (int b = 0; b < NB; ++b)
        hb[b] = (unsigned)__cvta_generic_to_shared(&hcat[0][b][0]);

    float c1 = 0.f, c2 = 0.f, xpre = 0.f;
    if (pre_lane && 1 < T) xpre = input[(b0 + q) * T + 1];    // x(1)

    __syncthreads();                       // init (hcat zero + xs) visible

    // a1n for t=0: bs1 + wi1*x(0)  (W_hh1·h1(-1) = 0)
    unsigned long long a1n[NB];
    #pragma unroll
    for (int b = 0; b < NB; ++b) a1n[b] = pack2(fmaf(xs[b], wi1, bs1), 0.f);

    // time loop unrolled by 2: even t -> cur buf0/prev buf1; odd t -> cur buf1/prev buf0
    for (int t = 0; t < Ttot; t += 2) {
        STEP(t,     0, 1, 0u,                   (unsigned)BUF_BYTES)
        STEP(t + 1, 1, 0, (unsigned)BUF_BYTES,  0u)
    }
}

extern "C" void kernel_launch(void* const* d_in, const int* in_sizes, int n_in,
                              void* d_out, int out_size) {
    const float* input = (const float*)d_in[0];
    const float* W_ih1 = (const float*)d_in[1];
    const float* W_hh1 = (const float*)d_in[2];
    const float* b_ih1 = (const float*)d_in[3];
    const float* b_hh1 = (const float*)d_in[4];
    const float* W_ih2 = (const float*)d_in[5];
    const float* W_hh2 = (const float*)d_in[6];
    const float* b_ih2 = (const float*)d_in[7];
    const float* b_hh2 = (const float*)d_in[8];
    const float* W_lin = (const float*)d_in[9];
    const float* b_lin = (const float*)d_in[10];

    const int T    = in_sizes[0] / BTOT;   // 1024
    const int Ttot = out_size    / BTOT;   // 1088 (even)

    lstm2_kernel<<<BTOT / NB, NTH>>>(input, W_ih1, W_hh1, b_ih1, b_hh1,
                                     W_ih2, W_hh2, b_ih2, b_hh2,
                                     W_lin, b_lin,
                                     (float*)d_out, T, Ttot);
}

// round 16
// speedup vs baseline: 1.0489x; 1.0489x over previous
#include <cuda_runtime.h>

#define Hh 51
#define NB 4
#define NTH 224
#define BTOT 512
#define ROWF 104                        // [0..50]=h1, [51]=x, [52..102]=h2, [103]=0
#define BUF_BYTES (NB * ROWF * 4)       // bytes per double-buffer half

__device__ __forceinline__ unsigned long long pack2(float lo, float hi) {
    unsigned long long r;
    asm("mov.b64 %0, {%1,%2};" : "=l"(r) : "f"(lo), "f"(hi));
    return r;
}
__device__ __forceinline__ void ffma2(unsigned long long &acc, unsigned long long a, unsigned long long b) {
    asm("fma.rn.f32x2 %0, %1, %2, %0;" : "+l"(acc) : "l"(a), "l"(b));
}
__device__ __forceinline__ float sum2(unsigned long long a) {
    float lo, hi;
    asm("mov.b64 {%0,%1}, %2;" : "=f"(lo), "=f"(hi) : "l"(a));
    return lo + hi;
}
__device__ __forceinline__ void lds128(unsigned long long &p0, unsigned long long &p1, unsigned addr) {
    asm volatile("ld.shared.v2.b64 {%0,%1}, [%2];" : "=l"(p0), "=l"(p1) : "r"(addr));
}
__device__ __forceinline__ float ftanh_(float x) {
    float r;
    asm("tanh.approx.f32 %0, %1;" : "=f"(r) : "f"(x));
    return r;
}

// 4x4 transpose across lane bits 3..4 (gate <-> batch-slot).
__device__ __forceinline__ void transp4(float v[4], int lane) {
    {
        bool lo = lane & 8;
        float tA = lo ? v[0] : v[1];
        float tB = lo ? v[2] : v[3];
        tA = __shfl_xor_sync(0xffffffffu, tA, 8);
        tB = __shfl_xor_sync(0xffffffffu, tB, 8);
        if (lo) { v[0] = tA; v[2] = tB; } else { v[1] = tA; v[3] = tB; }
    }
    {
        bool hi = lane & 16;
        float uA = hi ? v[0] : v[2];
        float uB = hi ? v[1] : v[3];
        uA = __shfl_xor_sync(0xffffffffu, uA, 16);
        uB = __shfl_xor_sync(0xffffffffu, uB, 16);
        if (hi) { v[0] = uA; v[1] = uB; } else { v[2] = uA; v[3] = uB; }
    }
}

#define REDUCE_PBUF(dst) { \
    float4 s4 = make_float4(0.f, 0.f, 0.f, 0.f); \
    const float4* p4 = (const float4*)&pbuf[q][0]; \
    _Pragma("unroll") for (int k = 0; k < 12; ++k) { \
        float4 v4 = p4[k]; \
        s4.x += v4.x; s4.y += v4.y; s4.z += v4.z; s4.w += v4.w; } \
    (dst) = (s4.x + s4.y) + (s4.z + s4.w) \
          + pbuf[q][48] + pbuf[q][49] + pbuf[q][50] + blin; }

// Pre-activation: apply MY gate's activation (uniform code, per-thread consts)
// to 4 batch values BEFORE the transpose. sig(x)=0.5+0.5*tanh(0.5x); tanh as-is.
#define PREACT(v) { \
    _Pragma("unroll") for (int b = 0; b < NB; ++b) \
        (v)[b] = fmaf(sa, ftanh_(sc * (v)[b]), sb); }

// One full timestep. CO/PO compile-time buffer byte-offsets; CI/PI buffer indices.
#define STEP(t, CI, PI, CO, PO) { \
    /* spare duties (warp 6), overlapped with phase A */ \
    if (pre_lane && ((t) + 1 < T)) \
        xpre = input[(b0 + q) * T + ((t) + 1)]; \
    if (red_lane && (t) >= 1 && (t) < T) { \
        float sres; REDUCE_PBUF(sres); \
        out[(b0 + q) * Ttot + ((t) - 1)] = sres; \
    } \
    /* tail-1 FIRST (independent of phase-A dot): layer-1 update from carried a1n + x(t) */ \
    float v[4]; \
    _Pragma("unroll") for (int b = 0; b < NB; ++b) \
        v[b] = fmaf(hcat[PI][b][51], wi1, sum2(a1n[b])); \
    PREACT(v) \
    transp4(v, lane);                       /* v = activated [i,f,g,o] for (batch q, j) */ \
    { \
        float cg = v[1] * c1 + v[0] * v[2]; \
        c1 = cg; \
        float h1 = v[3] * ftanh_(cg); \
        if (act) hcat[CI][q][j] = h1; \
    } \
    /* phase-A dot: a2 = bs2 + W_hh2 . h2(t-1)  (prev slots 52..103, static offsets) */ \
    unsigned long long a2[NB]; \
    _Pragma("unroll") for (int b = 0; b < NB; ++b) a2[b] = pack2(bs2, 0.f); \
    _Pragma("unroll") for (int kk = 0; kk < 13; ++kk) { \
        _Pragma("unroll") for (int b = 0; b < NB; ++b) { \
            unsigned long long q0, q1; \
            lds128(q0, q1, hb[b] + (PO) + 208u + kk * 16u); \
            ffma2(a2[b], w2p[26 + 2*kk], q0); \
            ffma2(a2[b], w2p[27 + 2*kk], q1); \
        } \
    } \
    __syncthreads();  /* B_A */ \
    /* phase B: joint dot over cur slots 0..51 (h1(t); slot 51 weight 0) */ \
    if (pre_lane && ((t) + 1 < T)) hcat[CI][q][51] = xpre; \
    _Pragma("unroll") for (int b = 0; b < NB; ++b) a1n[b] = pack2(bs1, 0.f); \
    _Pragma("unroll") for (int kk = 0; kk < 13; ++kk) { \
        _Pragma("unroll") for (int b = 0; b < NB; ++b) { \
            unsigned long long p0, p1; \
            lds128(p0, p1, hb[b] + (CO) + kk * 16u); \
            ffma2(a2[b],  w2p[2*kk],     p0); \
            ffma2(a2[b],  w2p[2*kk + 1], p1); \
            ffma2(a1n[b], w1n[2*kk],     p0); \
            ffma2(a1n[b], w1n[2*kk + 1], p1); \
        } \
    } \
    _Pragma("unroll") for (int b = 0; b < NB; ++b) v[b] = sum2(a2[b]); \
    PREACT(v) \
    transp4(v, lane); \
    { \
        float cg = v[1] * c2 + v[0] * v[2]; \
        c2 = cg; \
        float h2v = v[3] * ftanh_(cg); \
        if (act) { \
            hcat[CI][q][52 + j] = h2v; \
            pbuf[q][j] = wl * h2v; \
        } \
    } \
    __syncthreads();  /* B_B */ \
    /* autoregressive feedback: out(t) -> x(t+1) */ \
    if ((t) >= T - 1) { \
        if (red_lane) { \
            float sres; REDUCE_PBUF(sres); \
            out[(b0 + q) * Ttot + (t)] = sres; \
            hcat[CI][q][51] = sres; \
        } \
        __syncthreads();  /* B_C */ \
    } \
}

__global__ void __launch_bounds__(NTH, 1)
lstm2_kernel(const float* __restrict__ input,
             const float* __restrict__ W_ih1, const float* __restrict__ W_hh1,
             const float* __restrict__ b_ih1, const float* __restrict__ b_hh1,
             const float* __restrict__ W_ih2, const float* __restrict__ W_hh2,
             const float* __restrict__ b_ih2, const float* __restrict__ b_hh2,
             const float* __restrict__ W_lin, const float* __restrict__ b_lin,
             float* __restrict__ out, int T, int Ttot)
{
    __shared__ __align__(16) float hcat[2][NB][ROWF];   // double-buffered
    __shared__ __align__(16) float pbuf[NB][68];

    const int  tid  = threadIdx.x;
    const int  lane = tid & 31;
    const int  wid  = tid >> 5;
    const int  jloc = lane & 7;
    const int  q    = (lane >> 3) & 3;          // gate index for dots; batch index for update
    const int  j    = wid * 8 + jloc;
    const bool act  = (j < Hh);
    const int  b0   = blockIdx.x * NB;
    const int  row  = q * Hh + (act ? j : 0);

    // pre-activation constants for MY gate type (q==2 is the tanh 'g' gate)
    const float sc = (q == 2) ? 1.0f : 0.5f;
    const float sa = sc;
    const float sb = (q == 2) ? 0.0f : 0.5f;

    const bool pre_lane = (wid == 6) && (jloc == 3);    // x(t+1) prefetch, batch q
    const bool red_lane = (wid == 6) && (jloc == 4);    // output reduction, batch q

    for (int i = tid; i < 2 * NB * ROWF; i += NTH) (&hcat[0][0][0])[i] = 0.f;
    __syncthreads();                                    // order init before x(0) store
    if (tid < NB) hcat[1][tid][51] = input[(b0 + tid) * T];   // x(0) into prev-buffer of t=0

    // ---- weights, packed along K into 64-bit pairs (registers) ----
    unsigned long long w1n[26], w2p[52];
    {
        const float* r1 = W_hh1 + row * Hh;
        #pragma unroll
        for (int k = 0; k < 26; ++k) {
            int k0 = 2*k, k1 = 2*k + 1;
            float a = (act && k0 < 51) ? r1[k0] : 0.f;
            float b = (act && k1 < 51) ? r1[k1] : 0.f;
            w1n[k] = pack2(a, b);
        }
        const float* ri = W_ih2 + row * Hh;   // multiplies h1
        const float* rh = W_hh2 + row * Hh;   // multiplies h2
        #pragma unroll
        for (int k = 0; k < 52; ++k) {
            int k0 = 2*k, k1 = 2*k + 1;
            float a = 0.f, b = 0.f;
            if (act) {
                a = (k0 < 51) ? ri[k0] : ((k0 >= 52 && k0 <= 102) ? rh[k0 - 52] : 0.f);
                b = (k1 < 51) ? ri[k1] : ((k1 >= 52 && k1 <= 102) ? rh[k1 - 52] : 0.f);
            }
            w2p[k] = pack2(a, b);
        }
    }
    const float wi1  = act ? W_ih1[row] : 0.f;
    const float bs1  = act ? (b_ih1[row] + b_hh1[row]) : 0.f;
    const float bs2  = act ? (b_ih2[row] + b_hh2[row]) : 0.f;
    const float wl   = act ? W_lin[j] : 0.f;
    const float blin = b_lin[0];

    unsigned hb[NB];
    #pragma unroll
    for (int b = 0; b < NB; ++b)
        hb[b] = (unsigned)__cvta_generic_to_shared(&hcat[0][b][0]);

    float c1 = 0.f, c2 = 0.f, xpre = 0.f;
    unsigned long long a1n[NB];
    #pragma unroll
    for (int b = 0; b < NB; ++b) a1n[b] = pack2(bs1, 0.f);   // layer-1 gates for t=0 (W_hh1·0)

    __syncthreads();

    // time loop unrolled by 2: even t -> cur buf0/prev buf1; odd t -> cur buf1/prev buf0
    for (int t = 0; t < Ttot; t += 2) {
        STEP(t,     0, 1, 0u,                   (unsigned)BUF_BYTES)
        STEP(t + 1, 1, 0, (unsigned)BUF_BYTES,  0u)
    }
}

extern "C" void kernel_launch(void* const* d_in, const int* in_sizes, int n_in,
                              void* d_out, int out_size) {
    const float* input = (const float*)d_in[0];
    const float* W_ih1 = (const float*)d_in[1];
    const float* W_hh1 = (const float*)d_in[2];
    const float* b_ih1 = (const float*)d_in[3];
    const float* b_hh1 = (const float*)d_in[4];
    const float* W_ih2 = (const float*)d_in[5];
    const float* W_hh2 = (const float*)d_in[6];
    const float* b_ih2 = (const float*)d_in[7];
    const float* b_hh2 = (const float*)d_in[8];
    const float* W_lin = (const float*)d_in[9];
    const float* b_lin = (const float*)d_in[10];

    const int T    = in_sizes[0] / BTOT;   // 1024
    const int Ttot = out_size    / BTOT;   // 1088 (even)

    lstm2_kernel<<<BTOT / NB, NTH>>>(input, W_ih1, W_hh1, b_ih1, b_hh1,
                                     W_ih2, W_hh2, b_ih2, b_hh2,
                                     W_lin, b_lin,
                                     (float*)d_out, T, Ttot);
}